// round 7
// baseline (speedup 1.0000x reference)
#include <cuda_runtime.h>
#include <cstdint>

#define B_SZ 1024
#define N_SZ 256
#define D_SZ 256
#define M_SZ 768
#define NEG_VAL -1.0e10f

// Scratch (__device__ globals; no allocation allowed)
__device__ float g_att[B_SZ * M_SZ];              // attention output (B, 768)
__device__ float g_x[B_SZ * (M_SZ + D_SZ)];       // [LN(h), src]  (B, 1024)
__device__ float g_y[B_SZ * M_SZ];                // relu(x @ W1^T)
__device__ float g_part[3 * B_SZ * M_SZ];         // split-K partials

// ---------------------------------------------------------------------------
// K1: fused single-pass attention, online softmax, cp.async double-buffered.
// One CTA per batch; 16-row k-tiles; k read from HBM exactly once.
// Softmax p[] computed once per tile by warp 0, broadcast via SMEM.
// ---------------------------------------------------------------------------
#define TROWS 16
#define ATTN_SMEM ((2 * TROWS * M_SZ + N_SZ + TROWS + 20) * 4)

__device__ __forceinline__ void cp_async16(uint32_t saddr, const void* gaddr) {
    asm volatile("cp.async.cg.shared.global [%0], [%1], 16;\n" :: "r"(saddr), "l"(gaddr));
}
__device__ __forceinline__ void cp_commit() { asm volatile("cp.async.commit_group;\n"); }

__global__ __launch_bounds__(256) void attn_kernel(
    const float* __restrict__ seq, const float* __restrict__ seq_e,
    const float* __restrict__ seq_t, const unsigned int* __restrict__ mask,
    const float* __restrict__ shared_attn, float* __restrict__ attn_w_out)
{
    extern __shared__ float smem[];
    float* sK    = smem;                        // [2][TROWS][768]
    float* s_all = smem + 2 * TROWS * M_SZ;     // [256]
    float* ts    = s_all + N_SZ;                // [TROWS]
    float* sp    = ts + TROWS;                  // [TROWS + 1] (p values + sum)

    const int b    = blockIdx.x;
    const int tid  = threadIdx.x;
    const int lane = tid & 31;
    const int wrp  = tid >> 5;
    const size_t bbase = (size_t)b * N_SZ * D_SZ;

    // wk into registers: lane needs wk[lane + 32*kk]
    float w_r[24];
    #pragma unroll
    for (int kk = 0; kk < 24; kk++)
        w_r[kk] = __ldg(shared_attn + M_SZ + lane + (kk << 5));

    float a0 = 0.f, a1 = 0.f, a2 = 0.f;
    float lsum = 0.f, mval = -3.0e38f;

    // issue tile 0
    {
        #pragma unroll
        for (int u = 0; u < 12; u++) {
            int idx = u * 256 + tid;           // 0..3071 float4
            int r   = idx / 192;
            int pos = idx - r * 192;
            int seg = pos >> 6;
            int j4  = pos & 63;
            const float* base = (seg == 0) ? seq : ((seg == 1) ? seq_e : seq_t);
            uint32_t sa = (uint32_t)__cvta_generic_to_shared(sK + (r * 192 + pos) * 4);
            cp_async16(sa, base + bbase + (size_t)r * D_SZ + j4 * 4);
        }
        cp_commit();
    }

    for (int t = 0; t < N_SZ / TROWS; t++) {
        const int cur = t & 1;
        if (t + 1 < N_SZ / TROWS) {
            const int nxt = (t + 1) & 1;
            const int n0n = (t + 1) * TROWS;
            #pragma unroll
            for (int u = 0; u < 12; u++) {
                int idx = u * 256 + tid;
                int r   = idx / 192;
                int pos = idx - r * 192;
                int seg = pos >> 6;
                int j4  = pos & 63;
                const float* base = (seg == 0) ? seq : ((seg == 1) ? seq_e : seq_t);
                uint32_t sa = (uint32_t)__cvta_generic_to_shared(
                    sK + (nxt * TROWS * M_SZ) + (r * 192 + pos) * 4);
                cp_async16(sa, base + bbase + (size_t)(n0n + r) * D_SZ + j4 * 4);
            }
            cp_commit();
            asm volatile("cp.async.wait_group 1;\n");
        } else {
            asm volatile("cp.async.wait_group 0;\n");
        }
        __syncthreads();

        const float* kb = sK + cur * TROWS * M_SZ;
        const int n0 = t * TROWS;

        // scores: each warp handles 2 rows
        {
            const int r0 = wrp * 2;
            float p0 = 0.f, p1 = 0.f;
            #pragma unroll
            for (int kk = 0; kk < 24; kk++) {
                int e = lane + (kk << 5);
                float w = w_r[kk];
                p0 = fmaf(kb[r0 * M_SZ + e], w, p0);
                p1 = fmaf(kb[(r0 + 1) * M_SZ + e], w, p1);
            }
            #pragma unroll
            for (int o = 16; o > 0; o >>= 1) {
                p0 += __shfl_xor_sync(0xffffffffu, p0, o);
                p1 += __shfl_xor_sync(0xffffffffu, p1, o);
            }
            if (lane == 0) {
                float s0 = (mask[(size_t)b * N_SZ + n0 + r0] != 0u)     ? NEG_VAL : p0;
                float s1 = (mask[(size_t)b * N_SZ + n0 + r0 + 1] != 0u) ? NEG_VAL : p1;
                ts[r0] = s0;        ts[r0 + 1] = s1;
                s_all[n0 + r0] = s0; s_all[n0 + r0 + 1] = s1;
            }
        }
        __syncthreads();

        // new running max (identical in every thread, deterministic)
        float mt = mval;
        #pragma unroll
        for (int r = 0; r < TROWS; r++) mt = fmaxf(mt, ts[r]);

        // warp 0 computes p[] and their sum once; everyone else just rescales
        if (wrp == 0) {
            float v = (lane < TROWS) ? __expf(ts[lane] - mt) : 0.f;
            float tot = v;
            #pragma unroll
            for (int o = 16; o > 0; o >>= 1) tot += __shfl_xor_sync(0xffffffffu, tot, o);
            if (lane < TROWS) sp[lane] = v;
            if (lane == 0)    sp[TROWS] = tot;
        }
        if (mt > mval) {
            float sc = __expf(mval - mt);
            a0 *= sc; a1 *= sc; a2 *= sc; lsum *= sc;
            mval = mt;
        }
        __syncthreads();

        lsum += sp[TROWS];
        #pragma unroll
        for (int r = 0; r < TROWS; r++) {
            float p = sp[r];
            const float* kr = kb + r * M_SZ;
            a0 = fmaf(p, kr[tid],       a0);
            a1 = fmaf(p, kr[tid + 256], a1);
            a2 = fmaf(p, kr[tid + 512], a2);
        }
        __syncthreads();   // protect sK[cur] + ts/sp before next tile
    }

    float inv = 1.0f / lsum;
    attn_w_out[(size_t)b * N_SZ + tid] = __expf(s_all[tid] - mval) * inv;
    float* o = g_att + (size_t)b * M_SZ;
    o[tid]       = a0 * inv;
    o[tid + 256] = a1 * inv;
    o[tid + 512] = a2 * inv;
}

// ---------------------------------------------------------------------------
// Split-K SIMT GEMM: C_part[z][b][n] = sum_{k in chunk z} A[b][k] * W[n][k]
// Tile 128 batches x 64 outputs, Kt=32, micro 8x4 (strided: m=ty+16i, n=tx+16e)
// Conflict-free SMEM (rows padded to 33 floats); register-prefetch pipelining:
// next tile's LDGs are issued before the FMA loop so DRAM/L2 latency overlaps
// compute instead of serializing at the __syncthreads boundary.
// ---------------------------------------------------------------------------
template <int KD, int S>
__global__ __launch_bounds__(256, 2) void gemm_sk_kernel(
    const float* __restrict__ A, const float* __restrict__ W,
    float* __restrict__ part, int Nout)
{
    __shared__ float sA[128 * 33];
    __shared__ float sW[64 * 33];

    const int tid = threadIdx.x;
    const int tx = tid & 15, ty = tid >> 4;
    const int m0 = blockIdx.x * 128;
    const int n0 = blockIdx.y * 64;
    const int z  = blockIdx.z;
    constexpr int KT = KD / 32;
    const int kt0 = z * KT / S;
    const int kt1 = (z + 1) * KT / S;

    const int ra_r  = tid >> 3, ra_j = tid & 7;          // A-load coords (4 chunks)
    float4 ra[4], rw[2];

    // prologue: fetch first tile into registers
    {
        const int kc = kt0 * 32;
        #pragma unroll
        for (int u = 0; u < 4; u++)
            ra[u] = __ldg((const float4*)(A + (size_t)(m0 + u * 32 + ra_r) * KD + kc) + ra_j);
        #pragma unroll
        for (int u = 0; u < 2; u++)
            rw[u] = __ldg((const float4*)(W + (size_t)(n0 + u * 32 + ra_r) * KD + kc) + ra_j);
    }

    float acc[8][4];
    #pragma unroll
    for (int i = 0; i < 8; i++)
        #pragma unroll
        for (int e = 0; e < 4; e++) acc[i][e] = 0.f;

    for (int kt = kt0; kt < kt1; kt++) {
        // stage registers -> SMEM
        #pragma unroll
        for (int u = 0; u < 4; u++) {
            float* d = sA + (u * 32 + ra_r) * 33 + ra_j * 4;
            d[0] = ra[u].x; d[1] = ra[u].y; d[2] = ra[u].z; d[3] = ra[u].w;
        }
        #pragma unroll
        for (int u = 0; u < 2; u++) {
            float* d = sW + (u * 32 + ra_r) * 33 + ra_j * 4;
            d[0] = rw[u].x; d[1] = rw[u].y; d[2] = rw[u].z; d[3] = rw[u].w;
        }
        __syncthreads();

        // prefetch next tile (LDG latency hides under the FMA loop)
        if (kt + 1 < kt1) {
            const int kc = (kt + 1) * 32;
            #pragma unroll
            for (int u = 0; u < 4; u++)
                ra[u] = __ldg((const float4*)(A + (size_t)(m0 + u * 32 + ra_r) * KD + kc) + ra_j);
            #pragma unroll
            for (int u = 0; u < 2; u++)
                rw[u] = __ldg((const float4*)(W + (size_t)(n0 + u * 32 + ra_r) * KD + kc) + ra_j);
        }

        #pragma unroll 8
        for (int k = 0; k < 32; k++) {
            float wv[4], av[8];
            #pragma unroll
            for (int e = 0; e < 4; e++) wv[e] = sW[(tx + 16 * e) * 33 + k];
            #pragma unroll
            for (int i = 0; i < 8; i++) av[i] = sA[(ty + 16 * i) * 33 + k];
            #pragma unroll
            for (int i = 0; i < 8; i++)
                #pragma unroll
                for (int e = 0; e < 4; e++)
                    acc[i][e] = fmaf(av[i], wv[e], acc[i][e]);
        }
        __syncthreads();
    }

    float* p = part + (size_t)z * B_SZ * Nout;
    #pragma unroll
    for (int i = 0; i < 8; i++)
        #pragma unroll
        for (int e = 0; e < 4; e++)
            p[(size_t)(m0 + ty + 16 * i) * Nout + n0 + tx + 16 * e] = acc[i][e];
}

// ---------------------------------------------------------------------------
// Reduce kernels (fold split-K partials + epilogue)
// ---------------------------------------------------------------------------
__global__ __launch_bounds__(256) void reduce_fc_ln_kernel(
    const float* __restrict__ src, const float* __restrict__ src_t,
    const float* __restrict__ ln_w, const float* __restrict__ ln_b)
{
    __shared__ float red[8];
    const int b = blockIdx.x;
    const int tid = threadIdx.x;
    const int lane = tid & 31, wrp = tid >> 5;

    const float* p0 = g_part + (size_t)b * M_SZ;
    const float* p1 = p0 + (size_t)B_SZ * M_SZ;
    const float* p2 = p1 + (size_t)B_SZ * M_SZ;

    float x0 = p0[tid]       + p1[tid]       + p2[tid]       + src[(size_t)b * D_SZ + tid];
    float x1 = p0[tid + 256] + p1[tid + 256] + p2[tid + 256];
    float x2 = p0[tid + 512] + p1[tid + 512] + p2[tid + 512] + src_t[(size_t)b * D_SZ + tid];

    float s = x0 + x1 + x2;
    #pragma unroll
    for (int o = 16; o > 0; o >>= 1) s += __shfl_xor_sync(0xffffffffu, s, o);
    if (lane == 0) red[wrp] = s;
    __syncthreads();
    float mu = (red[0]+red[1]+red[2]+red[3]+red[4]+red[5]+red[6]+red[7]) * (1.0f/768.0f);
    __syncthreads();

    float d0 = x0 - mu, d1 = x1 - mu, d2 = x2 - mu;
    float q = d0*d0 + d1*d1 + d2*d2;
    #pragma unroll
    for (int o = 16; o > 0; o >>= 1) q += __shfl_xor_sync(0xffffffffu, q, o);
    if (lane == 0) red[wrp] = q;
    __syncthreads();
    float var = (red[0]+red[1]+red[2]+red[3]+red[4]+red[5]+red[6]+red[7]) * (1.0f/768.0f);
    float rstd = rsqrtf(var + 1e-5f);

    float* xo = g_x + (size_t)b * (M_SZ + D_SZ);
    xo[tid]       = d0 * rstd * ln_w[tid]       + ln_b[tid];
    xo[tid + 256] = d1 * rstd * ln_w[tid + 256] + ln_b[tid + 256];
    xo[tid + 512] = d2 * rstd * ln_w[tid + 512] + ln_b[tid + 512];
    xo[768 + tid] = src[(size_t)b * D_SZ + tid];
}

__global__ __launch_bounds__(256) void reduce_relu_kernel()
{
    const int b = blockIdx.x;
    const int tid = threadIdx.x;
    const float* p0 = g_part + (size_t)b * M_SZ;
    const float* p1 = p0 + (size_t)B_SZ * M_SZ;
    const float* p2 = p1 + (size_t)B_SZ * M_SZ;
    float* y = g_y + (size_t)b * M_SZ;
    #pragma unroll
    for (int c = 0; c < 3; c++) {
        int f = tid + c * 256;
        y[f] = fmaxf(p0[f] + p1[f] + p2[f], 0.f);
    }
}

__global__ __launch_bounds__(256) void reduce_out_kernel(float* __restrict__ out)
{
    const int b = blockIdx.x;
    const int tid = threadIdx.x;
    float s = 0.f;
    #pragma unroll
    for (int z = 0; z < 8; z++)
        s += g_part[(size_t)z * B_SZ * D_SZ + (size_t)b * D_SZ + tid];
    out[(size_t)b * D_SZ + tid] = s;
}

// ---------------------------------------------------------------------------
extern "C" void kernel_launch(void* const* d_in, const int* in_sizes, int n_in,
                              void* d_out, int out_size)
{
    const float* src         = (const float*)d_in[0];
    const float* src_t       = (const float*)d_in[1];
    const float* seq         = (const float*)d_in[2];
    const float* seq_t       = (const float*)d_in[3];
    const float* seq_e       = (const float*)d_in[4];
    const unsigned int* mask = (const unsigned int*)d_in[5];
    const float* shared_attn = (const float*)d_in[6];
    const float* fc_w        = (const float*)d_in[7];
    const float* ln_w        = (const float*)d_in[8];
    const float* ln_b        = (const float*)d_in[9];
    const float* w1          = (const float*)d_in[10];
    const float* w2          = (const float*)d_in[11];

    float* out    = (float*)d_out;
    float* attn_w = out + (size_t)B_SZ * D_SZ;

    float* g_att_p;  cudaGetSymbolAddress((void**)&g_att_p, g_att);
    float* g_x_p;    cudaGetSymbolAddress((void**)&g_x_p, g_x);
    float* g_y_p;    cudaGetSymbolAddress((void**)&g_y_p, g_y);
    float* g_part_p; cudaGetSymbolAddress((void**)&g_part_p, g_part);

    cudaFuncSetAttribute(attn_kernel, cudaFuncAttributeMaxDynamicSharedMemorySize, ATTN_SMEM);

    attn_kernel<<<B_SZ, 256, ATTN_SMEM>>>(seq, seq_e, seq_t, mask, shared_attn, attn_w);

    gemm_sk_kernel<768, 3><<<dim3(8, 12, 3), 256>>>(g_att_p, fc_w, g_part_p, M_SZ);
    reduce_fc_ln_kernel<<<B_SZ, 256>>>(src, src_t, ln_w, ln_b);

    gemm_sk_kernel<1024, 3><<<dim3(8, 12, 3), 256>>>(g_x_p, w1, g_part_p, M_SZ);
    reduce_relu_kernel<<<B_SZ, 256>>>();

    gemm_sk_kernel<768, 8><<<dim3(8, 4, 8), 256>>>(g_y_p, w2, g_part_p, D_SZ);
    reduce_out_kernel<<<B_SZ, 256>>>(out);
}

// round 9
// speedup vs baseline: 1.0156x; 1.0156x over previous
#include <cuda_runtime.h>
#include <cstdint>

#define B_SZ 1024
#define N_SZ 256
#define D_SZ 256
#define M_SZ 768
#define NEG_VAL -1.0e10f

// Scratch (__device__ globals; no allocation allowed)
__device__ float g_att[B_SZ * M_SZ];              // attention output (B, 768)
__device__ float g_x[B_SZ * (M_SZ + D_SZ)];       // [LN(h), src]  (B, 1024)
__device__ float g_y[B_SZ * M_SZ];                // relu(x @ W1^T)
__device__ float g_part[3 * B_SZ * M_SZ];         // split-K partials

// ---------------------------------------------------------------------------
// K1: fused single-pass attention, online softmax, cp.async double-buffered.
// One CTA per batch; 16-row k-tiles; k read from HBM exactly once.
// Accumulate loop uses paired features (LDS.64) to cut issue slots.
// ---------------------------------------------------------------------------
#define TROWS 16
#define ATTN_SMEM ((2 * TROWS * M_SZ + N_SZ + TROWS + 20) * 4)

__device__ __forceinline__ void cp_async16(uint32_t saddr, const void* gaddr) {
    asm volatile("cp.async.cg.shared.global [%0], [%1], 16;\n" :: "r"(saddr), "l"(gaddr));
}
__device__ __forceinline__ void cp_commit() { asm volatile("cp.async.commit_group;\n"); }

__global__ __launch_bounds__(256) void attn_kernel(
    const float* __restrict__ seq, const float* __restrict__ seq_e,
    const float* __restrict__ seq_t, const unsigned int* __restrict__ mask,
    const float* __restrict__ shared_attn, float* __restrict__ attn_w_out)
{
    extern __shared__ float smem[];
    float* sK    = smem;                        // [2][TROWS][768]
    float* s_all = smem + 2 * TROWS * M_SZ;     // [256]
    float* ts    = s_all + N_SZ;                // [TROWS]
    float* sp    = ts + TROWS;                  // [TROWS + 1] (p values + sum)

    const int b    = blockIdx.x;
    const int tid  = threadIdx.x;
    const int lane = tid & 31;
    const int wrp  = tid >> 5;
    const size_t bbase = (size_t)b * N_SZ * D_SZ;

    // wk into registers: lane needs wk[lane + 32*kk]
    float w_r[24];
    #pragma unroll
    for (int kk = 0; kk < 24; kk++)
        w_r[kk] = __ldg(shared_attn + M_SZ + lane + (kk << 5));

    // thread owns features (2*tid, 2*tid+1) and (512 + tid)
    float2 a01 = make_float2(0.f, 0.f);
    float  a2  = 0.f;
    float lsum = 0.f, mval = -3.0e38f;

    // issue tile 0
    {
        #pragma unroll
        for (int u = 0; u < 12; u++) {
            int idx = u * 256 + tid;           // 0..3071 float4
            int r   = idx / 192;
            int pos = idx - r * 192;
            int seg = pos >> 6;
            int j4  = pos & 63;
            const float* base = (seg == 0) ? seq : ((seg == 1) ? seq_e : seq_t);
            uint32_t sa = (uint32_t)__cvta_generic_to_shared(sK + (r * 192 + pos) * 4);
            cp_async16(sa, base + bbase + (size_t)r * D_SZ + j4 * 4);
        }
        cp_commit();
    }

    for (int t = 0; t < N_SZ / TROWS; t++) {
        const int cur = t & 1;
        if (t + 1 < N_SZ / TROWS) {
            const int nxt = (t + 1) & 1;
            const int n0n = (t + 1) * TROWS;
            #pragma unroll
            for (int u = 0; u < 12; u++) {
                int idx = u * 256 + tid;
                int r   = idx / 192;
                int pos = idx - r * 192;
                int seg = pos >> 6;
                int j4  = pos & 63;
                const float* base = (seg == 0) ? seq : ((seg == 1) ? seq_e : seq_t);
                uint32_t sa = (uint32_t)__cvta_generic_to_shared(
                    sK + (nxt * TROWS * M_SZ) + (r * 192 + pos) * 4);
                cp_async16(sa, base + bbase + (size_t)(n0n + r) * D_SZ + j4 * 4);
            }
            cp_commit();
            asm volatile("cp.async.wait_group 1;\n");
        } else {
            asm volatile("cp.async.wait_group 0;\n");
        }
        __syncthreads();

        const float* kb = sK + cur * TROWS * M_SZ;
        const int n0 = t * TROWS;

        // scores: each warp handles 2 rows
        {
            const int r0 = wrp * 2;
            float p0 = 0.f, p1 = 0.f;
            #pragma unroll
            for (int kk = 0; kk < 24; kk++) {
                int e = lane + (kk << 5);
                float w = w_r[kk];
                p0 = fmaf(kb[r0 * M_SZ + e], w, p0);
                p1 = fmaf(kb[(r0 + 1) * M_SZ + e], w, p1);
            }
            #pragma unroll
            for (int o = 16; o > 0; o >>= 1) {
                p0 += __shfl_xor_sync(0xffffffffu, p0, o);
                p1 += __shfl_xor_sync(0xffffffffu, p1, o);
            }
            if (lane == 0) {
                float s0 = (mask[(size_t)b * N_SZ + n0 + r0] != 0u)     ? NEG_VAL : p0;
                float s1 = (mask[(size_t)b * N_SZ + n0 + r0 + 1] != 0u) ? NEG_VAL : p1;
                ts[r0] = s0;        ts[r0 + 1] = s1;
                s_all[n0 + r0] = s0; s_all[n0 + r0 + 1] = s1;
            }
        }
        __syncthreads();

        // new running max (identical in every thread, deterministic)
        float mt = mval;
        #pragma unroll
        for (int r = 0; r < TROWS; r++) mt = fmaxf(mt, ts[r]);

        // warp 0 computes p[] and their sum once; everyone else just rescales
        if (wrp == 0) {
            float v = (lane < TROWS) ? __expf(ts[lane] - mt) : 0.f;
            float tot = v;
            #pragma unroll
            for (int o = 16; o > 0; o >>= 1) tot += __shfl_xor_sync(0xffffffffu, tot, o);
            if (lane < TROWS) sp[lane] = v;
            if (lane == 0)    sp[TROWS] = tot;
        }
        if (mt > mval) {
            float sc = __expf(mval - mt);
            a01.x *= sc; a01.y *= sc; a2 *= sc; lsum *= sc;
            mval = mt;
        }
        __syncthreads();

        lsum += sp[TROWS];
        #pragma unroll
        for (int r = 0; r < TROWS; r++) {
            float p = sp[r];
            const float* kr = kb + r * M_SZ;
            float2 kv = *(const float2*)(kr + 2 * tid);
            a01.x = fmaf(p, kv.x, a01.x);
            a01.y = fmaf(p, kv.y, a01.y);
            a2    = fmaf(p, kr[512 + tid], a2);
        }
        __syncthreads();   // protect sK[cur] + ts/sp before next tile
    }

    float inv = 1.0f / lsum;
    attn_w_out[(size_t)b * N_SZ + tid] = __expf(s_all[tid] - mval) * inv;
    float* o = g_att + (size_t)b * M_SZ;
    *(float2*)(o + 2 * tid) = make_float2(a01.x * inv, a01.y * inv);
    o[512 + tid] = a2 * inv;
}

// ---------------------------------------------------------------------------
// Split-K SIMT GEMM: C_part[z][b][n] = sum_{k in chunk z} A[b][k] * W[n][k]
// Tile 128 batches x 64 outputs, Kt=32, micro 8x4 (strided: m=ty+16i, n=tx+16e)
// SMEM rows padded to 36 floats: 16B-aligned rows -> all compute loads and the
// staging stores are LDS.128/STS.128, conflict-free (bank = (4*row + k) % 32
// covers all 32 banks once per 8-thread phase). Register-prefetch pipelining
// overlaps next tile's LDGs with the FMA loop.
// ---------------------------------------------------------------------------
template <int KD, int S>
__global__ __launch_bounds__(256, 2) void gemm_sk_kernel(
    const float* __restrict__ A, const float* __restrict__ W,
    float* __restrict__ part, int Nout)
{
    __shared__ __align__(16) float sA[128 * 36];
    __shared__ __align__(16) float sW[64 * 36];

    const int tid = threadIdx.x;
    const int tx = tid & 15, ty = tid >> 4;
    const int m0 = blockIdx.x * 128;
    const int n0 = blockIdx.y * 64;
    const int z  = blockIdx.z;
    constexpr int KT = KD / 32;
    const int kt0 = z * KT / S;
    const int kt1 = (z + 1) * KT / S;

    const int ra_r = tid >> 3, ra_j = tid & 7;          // load coords
    float4 ra[4], rw[2];

    // prologue: fetch first tile into registers
    {
        const int kc = kt0 * 32;
        #pragma unroll
        for (int u = 0; u < 4; u++)
            ra[u] = __ldg((const float4*)(A + (size_t)(m0 + u * 32 + ra_r) * KD + kc) + ra_j);
        #pragma unroll
        for (int u = 0; u < 2; u++)
            rw[u] = __ldg((const float4*)(W + (size_t)(n0 + u * 32 + ra_r) * KD + kc) + ra_j);
    }

    float acc[8][4];
    #pragma unroll
    for (int i = 0; i < 8; i++)
        #pragma unroll
        for (int e = 0; e < 4; e++) acc[i][e] = 0.f;

    for (int kt = kt0; kt < kt1; kt++) {
        // stage registers -> SMEM (STS.128, aligned: (36r + 4j)*4 % 16 == 0)
        #pragma unroll
        for (int u = 0; u < 4; u++)
            *(float4*)(sA + (u * 32 + ra_r) * 36 + ra_j * 4) = ra[u];
        #pragma unroll
        for (int u = 0; u < 2; u++)
            *(float4*)(sW + (u * 32 + ra_r) * 36 + ra_j * 4) = rw[u];
        __syncthreads();

        // prefetch next tile (LDG latency hides under the FMA loop)
        if (kt + 1 < kt1) {
            const int kc = (kt + 1) * 32;
            #pragma unroll
            for (int u = 0; u < 4; u++)
                ra[u] = __ldg((const float4*)(A + (size_t)(m0 + u * 32 + ra_r) * KD + kc) + ra_j);
            #pragma unroll
            for (int u = 0; u < 2; u++)
                rw[u] = __ldg((const float4*)(W + (size_t)(n0 + u * 32 + ra_r) * KD + kc) + ra_j);
        }

        // 8 k-quads; LDS.128 operand loads
        #pragma unroll
        for (int k4 = 0; k4 < 8; k4++) {
            float4 wv[4];
            #pragma unroll
            for (int e = 0; e < 4; e++)
                wv[e] = *(const float4*)(sW + (tx + 16 * e) * 36 + 4 * k4);
            // two halves of 4 m-values to bound register pressure
            #pragma unroll
            for (int h = 0; h < 2; h++) {
                float4 av[4];
                #pragma unroll
                for (int i = 0; i < 4; i++)
                    av[i] = *(const float4*)(sA + (ty + 16 * (h * 4 + i)) * 36 + 4 * k4);
                #pragma unroll
                for (int i = 0; i < 4; i++)
                    #pragma unroll
                    for (int e = 0; e < 4; e++) {
                        float s = acc[h * 4 + i][e];
                        s = fmaf(av[i].x, wv[e].x, s);
                        s = fmaf(av[i].y, wv[e].y, s);
                        s = fmaf(av[i].z, wv[e].z, s);
                        s = fmaf(av[i].w, wv[e].w, s);
                        acc[h * 4 + i][e] = s;
                    }
            }
        }
        __syncthreads();
    }

    float* p = part + (size_t)z * B_SZ * Nout;
    #pragma unroll
    for (int i = 0; i < 8; i++)
        #pragma unroll
        for (int e = 0; e < 4; e++)
            p[(size_t)(m0 + ty + 16 * i) * Nout + n0 + tx + 16 * e] = acc[i][e];
}

// ---------------------------------------------------------------------------
// Reduce kernels (fold split-K partials + epilogue)
// ---------------------------------------------------------------------------
__global__ __launch_bounds__(256) void reduce_fc_ln_kernel(
    const float* __restrict__ src, const float* __restrict__ src_t,
    const float* __restrict__ ln_w, const float* __restrict__ ln_b)
{
    __shared__ float red[8];
    const int b = blockIdx.x;
    const int tid = threadIdx.x;
    const int lane = tid & 31, wrp = tid >> 5;

    const float* p0 = g_part + (size_t)b * M_SZ;
    const float* p1 = p0 + (size_t)B_SZ * M_SZ;
    const float* p2 = p1 + (size_t)B_SZ * M_SZ;

    float x0 = p0[tid]       + p1[tid]       + p2[tid]       + src[(size_t)b * D_SZ + tid];
    float x1 = p0[tid + 256] + p1[tid + 256] + p2[tid + 256];
    float x2 = p0[tid + 512] + p1[tid + 512] + p2[tid + 512] + src_t[(size_t)b * D_SZ + tid];

    float s = x0 + x1 + x2;
    #pragma unroll
    for (int o = 16; o > 0; o >>= 1) s += __shfl_xor_sync(0xffffffffu, s, o);
    if (lane == 0) red[wrp] = s;
    __syncthreads();
    float mu = (red[0]+red[1]+red[2]+red[3]+red[4]+red[5]+red[6]+red[7]) * (1.0f/768.0f);
    __syncthreads();

    float d0 = x0 - mu, d1 = x1 - mu, d2 = x2 - mu;
    float q = d0*d0 + d1*d1 + d2*d2;
    #pragma unroll
    for (int o = 16; o > 0; o >>= 1) q += __shfl_xor_sync(0xffffffffu, q, o);
    if (lane == 0) red[wrp] = q;
    __syncthreads();
    float var = (red[0]+red[1]+red[2]+red[3]+red[4]+red[5]+red[6]+red[7]) * (1.0f/768.0f);
    float rstd = rsqrtf(var + 1e-5f);

    float* xo = g_x + (size_t)b * (M_SZ + D_SZ);
    xo[tid]       = d0 * rstd * ln_w[tid]       + ln_b[tid];
    xo[tid + 256] = d1 * rstd * ln_w[tid + 256] + ln_b[tid + 256];
    xo[tid + 512] = d2 * rstd * ln_w[tid + 512] + ln_b[tid + 512];
    xo[768 + tid] = src[(size_t)b * D_SZ + tid];
}

__global__ __launch_bounds__(256) void reduce_relu_kernel()
{
    const int b = blockIdx.x;
    const int tid = threadIdx.x;
    const float* p0 = g_part + (size_t)b * M_SZ;
    const float* p1 = p0 + (size_t)B_SZ * M_SZ;
    const float* p2 = p1 + (size_t)B_SZ * M_SZ;
    float* y = g_y + (size_t)b * M_SZ;
    #pragma unroll
    for (int c = 0; c < 3; c++) {
        int f = tid + c * 256;
        y[f] = fmaxf(p0[f] + p1[f] + p2[f], 0.f);
    }
}

__global__ __launch_bounds__(256) void reduce_out_kernel(float* __restrict__ out)
{
    const int b = blockIdx.x;
    const int tid = threadIdx.x;
    float s = 0.f;
    #pragma unroll
    for (int z = 0; z < 8; z++)
        s += g_part[(size_t)z * B_SZ * D_SZ + (size_t)b * D_SZ + tid];
    out[(size_t)b * D_SZ + tid] = s;
}

// ---------------------------------------------------------------------------
extern "C" void kernel_launch(void* const* d_in, const int* in_sizes, int n_in,
                              void* d_out, int out_size)
{
    const float* src         = (const float*)d_in[0];
    const float* src_t       = (const float*)d_in[1];
    const float* seq         = (const float*)d_in[2];
    const float* seq_t       = (const float*)d_in[3];
    const float* seq_e       = (const float*)d_in[4];
    const unsigned int* mask = (const unsigned int*)d_in[5];
    const float* shared_attn = (const float*)d_in[6];
    const float* fc_w        = (const float*)d_in[7];
    const float* ln_w        = (const float*)d_in[8];
    const float* ln_b        = (const float*)d_in[9];
    const float* w1          = (const float*)d_in[10];
    const float* w2          = (const float*)d_in[11];

    float* out    = (float*)d_out;
    float* attn_w = out + (size_t)B_SZ * D_SZ;

    float* g_att_p;  cudaGetSymbolAddress((void**)&g_att_p, g_att);
    float* g_x_p;    cudaGetSymbolAddress((void**)&g_x_p, g_x);
    float* g_y_p;    cudaGetSymbolAddress((void**)&g_y_p, g_y);
    float* g_part_p; cudaGetSymbolAddress((void**)&g_part_p, g_part);

    cudaFuncSetAttribute(attn_kernel, cudaFuncAttributeMaxDynamicSharedMemorySize, ATTN_SMEM);

    attn_kernel<<<B_SZ, 256, ATTN_SMEM>>>(seq, seq_e, seq_t, mask, shared_attn, attn_w);

    gemm_sk_kernel<768, 3><<<dim3(8, 12, 3), 256>>>(g_att_p, fc_w, g_part_p, M_SZ);
    reduce_fc_ln_kernel<<<B_SZ, 256>>>(src, src_t, ln_w, ln_b);

    gemm_sk_kernel<1024, 3><<<dim3(8, 12, 3), 256>>>(g_x_p, w1, g_part_p, M_SZ);
    reduce_relu_kernel<<<B_SZ, 256>>>();

    gemm_sk_kernel<768, 8><<<dim3(8, 4, 8), 256>>>(g_y_p, w2, g_part_p, D_SZ);
    reduce_out_kernel<<<B_SZ, 256>>>(out);
}

// round 10
// speedup vs baseline: 1.2412x; 1.2221x over previous
#include <cuda_runtime.h>
#include <cstdint>

#define B_SZ 1024
#define N_SZ 256
#define D_SZ 256
#define M_SZ 768
#define NEG_VAL -1.0e10f

// Scratch (__device__ globals; no allocation allowed)
__device__ float g_att[B_SZ * M_SZ];              // attention output (B, 768)
__device__ float g_x[B_SZ * (M_SZ + D_SZ)];       // [LN(h), src]  (B, 1024)
__device__ float g_y[B_SZ * M_SZ];                // relu(x @ W1^T)
__device__ float g_part[3 * B_SZ * M_SZ];         // split-K partials

// ---------------------------------------------------------------------------
// K1: fused single-pass attention, online softmax, cp.async double-buffered.
// TROWS=8 -> ~49KB smem -> 4 CTAs/SM for deeper memory pipelining.
// ---------------------------------------------------------------------------
#define TROWS 8
#define ATTN_SMEM ((2 * TROWS * M_SZ + N_SZ + TROWS + 12) * 4)

__device__ __forceinline__ void cp_async16(uint32_t saddr, const void* gaddr) {
    asm volatile("cp.async.cg.shared.global [%0], [%1], 16;\n" :: "r"(saddr), "l"(gaddr));
}
__device__ __forceinline__ void cp_commit() { asm volatile("cp.async.commit_group;\n"); }

__global__ __launch_bounds__(256) void attn_kernel(
    const float* __restrict__ seq, const float* __restrict__ seq_e,
    const float* __restrict__ seq_t, const unsigned int* __restrict__ mask,
    const float* __restrict__ shared_attn, float* __restrict__ attn_w_out)
{
    extern __shared__ float smem[];
    float* sK    = smem;                        // [2][TROWS][768]
    float* s_all = smem + 2 * TROWS * M_SZ;     // [256]
    float* ts    = s_all + N_SZ;                // [TROWS]
    float* sp    = ts + TROWS;                  // [TROWS + 1]

    const int b    = blockIdx.x;
    const int tid  = threadIdx.x;
    const int lane = tid & 31;
    const int wrp  = tid >> 5;
    const size_t bbase = (size_t)b * N_SZ * D_SZ;

    // wk in registers: lane needs wk[lane + 32*kk]
    float w_r[24];
    #pragma unroll
    for (int kk = 0; kk < 24; kk++)
        w_r[kk] = __ldg(shared_attn + M_SZ + lane + (kk << 5));

    float2 a01 = make_float2(0.f, 0.f);      // features 2*tid, 2*tid+1
    float  a2  = 0.f;                        // feature 512+tid
    float lsum = 0.f, mval = -3.0e38f;

    // issue tile 0 (8 rows x 768 floats = 1536 float4 / 256 threads = 6 chunks)
    {
        #pragma unroll
        for (int u = 0; u < 6; u++) {
            int idx = u * 256 + tid;
            int r   = idx / 192;
            int pos = idx - r * 192;
            int seg = pos >> 6;
            int j4  = pos & 63;
            const float* base = (seg == 0) ? seq : ((seg == 1) ? seq_e : seq_t);
            uint32_t sa = (uint32_t)__cvta_generic_to_shared(sK + (r * 192 + pos) * 4);
            cp_async16(sa, base + bbase + (size_t)r * D_SZ + j4 * 4);
        }
        cp_commit();
    }

    for (int t = 0; t < N_SZ / TROWS; t++) {
        const int cur = t & 1;
        if (t + 1 < N_SZ / TROWS) {
            const int nxt = (t + 1) & 1;
            const int n0n = (t + 1) * TROWS;
            #pragma unroll
            for (int u = 0; u < 6; u++) {
                int idx = u * 256 + tid;
                int r   = idx / 192;
                int pos = idx - r * 192;
                int seg = pos >> 6;
                int j4  = pos & 63;
                const float* base = (seg == 0) ? seq : ((seg == 1) ? seq_e : seq_t);
                uint32_t sa = (uint32_t)__cvta_generic_to_shared(
                    sK + (nxt * TROWS * M_SZ) + (r * 192 + pos) * 4);
                cp_async16(sa, base + bbase + (size_t)(n0n + r) * D_SZ + j4 * 4);
            }
            cp_commit();
            asm volatile("cp.async.wait_group 1;\n");
        } else {
            asm volatile("cp.async.wait_group 0;\n");
        }
        __syncthreads();

        const float* kb = sK + cur * TROWS * M_SZ;
        const int n0 = t * TROWS;

        // scores: warp w handles row w
        {
            float part = 0.f;
            const float* kr = kb + wrp * M_SZ;
            #pragma unroll
            for (int kk = 0; kk < 24; kk++)
                part = fmaf(kr[lane + (kk << 5)], w_r[kk], part);
            #pragma unroll
            for (int o = 16; o > 0; o >>= 1)
                part += __shfl_xor_sync(0xffffffffu, part, o);
            if (lane == 0) {
                int n = n0 + wrp;
                float s = (mask[(size_t)b * N_SZ + n] != 0u) ? NEG_VAL : part;
                ts[wrp]  = s;
                s_all[n] = s;
            }
        }
        __syncthreads();

        // new running max (identical in every thread, deterministic)
        float mt = mval;
        #pragma unroll
        for (int r = 0; r < TROWS; r++) mt = fmaxf(mt, ts[r]);

        // warp 0 computes p[] + sum once
        if (wrp == 0) {
            float v = (lane < TROWS) ? __expf(ts[lane] - mt) : 0.f;
            float tot = v;
            #pragma unroll
            for (int o = 16; o > 0; o >>= 1) tot += __shfl_xor_sync(0xffffffffu, tot, o);
            if (lane < TROWS) sp[lane] = v;
            if (lane == 0)    sp[TROWS] = tot;
        }
        if (mt > mval) {
            float sc = __expf(mval - mt);
            a01.x *= sc; a01.y *= sc; a2 *= sc; lsum *= sc;
            mval = mt;
        }
        __syncthreads();

        lsum += sp[TROWS];
        #pragma unroll
        for (int r = 0; r < TROWS; r++) {
            float p = sp[r];
            const float* kr = kb + r * M_SZ;
            float2 kv = *(const float2*)(kr + 2 * tid);
            a01.x = fmaf(p, kv.x, a01.x);
            a01.y = fmaf(p, kv.y, a01.y);
            a2    = fmaf(p, kr[512 + tid], a2);
        }
        __syncthreads();
    }

    float inv = 1.0f / lsum;
    attn_w_out[(size_t)b * N_SZ + tid] = __expf(s_all[tid] - mval) * inv;
    float* o = g_att + (size_t)b * M_SZ;
    *(float2*)(o + 2 * tid) = make_float2(a01.x * inv, a01.y * inv);
    o[512 + tid] = a2 * inv;
}

// ---------------------------------------------------------------------------
// Split-K tf32 tensor-core GEMM: C_part[z][b][n] = sum_k A[b][k] * W[n][k]
// CTA tile 128(m) x 64(n), Kt=32. 8 warps as 2(m) x 4(n); each warp:
// 4 m16 tiles x 2 n8 tiles via mma.sync.m16n8k8.tf32.
// Operands cvt.rna to tf32 at SMEM staging. Row stride 36 u32 (16B-aligned,
// conflict-free for both STS.128 staging and fragment LDS.32 gathers).
// ---------------------------------------------------------------------------
__device__ __forceinline__ uint32_t f2tf32(float x) {
    uint32_t r; asm("cvt.rna.tf32.f32 %0, %1;\n" : "=r"(r) : "f"(x)); return r;
}
__device__ __forceinline__ void mma_tf32(float* c, const uint32_t* a, const uint32_t* b) {
    asm volatile(
        "mma.sync.aligned.m16n8k8.row.col.f32.tf32.tf32.f32 "
        "{%0,%1,%2,%3}, {%4,%5,%6,%7}, {%8,%9}, {%0,%1,%2,%3};\n"
        : "+f"(c[0]), "+f"(c[1]), "+f"(c[2]), "+f"(c[3])
        : "r"(a[0]), "r"(a[1]), "r"(a[2]), "r"(a[3]), "r"(b[0]), "r"(b[1]));
}

template <int KD, int S>
__global__ __launch_bounds__(256, 2) void gemm_tc_kernel(
    const float* __restrict__ A, const float* __restrict__ W,
    float* __restrict__ part, int Nout)
{
    __shared__ __align__(16) uint32_t sA[128 * 36];
    __shared__ __align__(16) uint32_t sW[64 * 36];

    const int tid  = threadIdx.x;
    const int wid  = tid >> 5, lane = tid & 31;
    const int g    = lane >> 2, tg = lane & 3;      // groupID, threadID_in_group
    const int wm   = wid & 1,  wn  = wid >> 1;      // 2 x 4 warp grid
    const int m0   = blockIdx.x * 128;
    const int n0   = blockIdx.y * 64;
    const int z    = blockIdx.z;
    constexpr int KT = KD / 32;
    const int kt0 = z * KT / S;
    const int kt1 = (z + 1) * KT / S;

    const int ra_r = tid >> 3, ra_j = tid & 7;      // staging coords
    float4 ra[4], rw[2];

    // prologue: fetch first tile
    {
        const int kc = kt0 * 32;
        #pragma unroll
        for (int u = 0; u < 4; u++)
            ra[u] = __ldg((const float4*)(A + (size_t)(m0 + u * 32 + ra_r) * KD + kc) + ra_j);
        #pragma unroll
        for (int u = 0; u < 2; u++)
            rw[u] = __ldg((const float4*)(W + (size_t)(n0 + u * 32 + ra_r) * KD + kc) + ra_j);
    }

    float acc[4][2][4];
    #pragma unroll
    for (int mi = 0; mi < 4; mi++)
        #pragma unroll
        for (int ni = 0; ni < 2; ni++)
            #pragma unroll
            for (int f = 0; f < 4; f++) acc[mi][ni][f] = 0.f;

    for (int kt = kt0; kt < kt1; kt++) {
        // stage (cvt to tf32) -> SMEM
        #pragma unroll
        for (int u = 0; u < 4; u++) {
            uint4 v = make_uint4(f2tf32(ra[u].x), f2tf32(ra[u].y), f2tf32(ra[u].z), f2tf32(ra[u].w));
            *(uint4*)(sA + (u * 32 + ra_r) * 36 + ra_j * 4) = v;
        }
        #pragma unroll
        for (int u = 0; u < 2; u++) {
            uint4 v = make_uint4(f2tf32(rw[u].x), f2tf32(rw[u].y), f2tf32(rw[u].z), f2tf32(rw[u].w));
            *(uint4*)(sW + (u * 32 + ra_r) * 36 + ra_j * 4) = v;
        }
        __syncthreads();

        // prefetch next tile
        if (kt + 1 < kt1) {
            const int kc = (kt + 1) * 32;
            #pragma unroll
            for (int u = 0; u < 4; u++)
                ra[u] = __ldg((const float4*)(A + (size_t)(m0 + u * 32 + ra_r) * KD + kc) + ra_j);
            #pragma unroll
            for (int u = 0; u < 2; u++)
                rw[u] = __ldg((const float4*)(W + (size_t)(n0 + u * 32 + ra_r) * KD + kc) + ra_j);
        }

        // 4 k8 steps
        #pragma unroll
        for (int ks = 0; ks < 4; ks++) {
            const int kb = ks * 8;
            uint32_t bfrag[2][2];
            #pragma unroll
            for (int ni = 0; ni < 2; ni++) {
                const int n = wn * 16 + ni * 8;
                bfrag[ni][0] = sW[(n + g) * 36 + kb + tg];
                bfrag[ni][1] = sW[(n + g) * 36 + kb + tg + 4];
            }
            #pragma unroll
            for (int mi = 0; mi < 4; mi++) {
                const int m = wm * 64 + mi * 16;
                uint32_t afrag[4];
                afrag[0] = sA[(m + g)     * 36 + kb + tg];
                afrag[1] = sA[(m + g + 8) * 36 + kb + tg];
                afrag[2] = sA[(m + g)     * 36 + kb + tg + 4];
                afrag[3] = sA[(m + g + 8) * 36 + kb + tg + 4];
                #pragma unroll
                for (int ni = 0; ni < 2; ni++)
                    mma_tf32(acc[mi][ni], afrag, bfrag[ni]);
            }
        }
        __syncthreads();
    }

    // epilogue: c0,c1 -> (g, 2tg..2tg+1); c2,c3 -> (g+8, 2tg..2tg+1)
    float* p = part + (size_t)z * B_SZ * Nout;
    #pragma unroll
    for (int mi = 0; mi < 4; mi++) {
        const int m = m0 + wm * 64 + mi * 16;
        #pragma unroll
        for (int ni = 0; ni < 2; ni++) {
            const int n = n0 + wn * 16 + ni * 8 + tg * 2;
            *(float2*)(p + (size_t)(m + g)     * Nout + n) = make_float2(acc[mi][ni][0], acc[mi][ni][1]);
            *(float2*)(p + (size_t)(m + g + 8) * Nout + n) = make_float2(acc[mi][ni][2], acc[mi][ni][3]);
        }
    }
}

// ---------------------------------------------------------------------------
// Reduce kernels (fold split-K partials + epilogue)
// ---------------------------------------------------------------------------
__global__ __launch_bounds__(256) void reduce_fc_ln_kernel(
    const float* __restrict__ src, const float* __restrict__ src_t,
    const float* __restrict__ ln_w, const float* __restrict__ ln_b)
{
    __shared__ float red[8];
    const int b = blockIdx.x;
    const int tid = threadIdx.x;
    const int lane = tid & 31, wrp = tid >> 5;

    const float* p0 = g_part + (size_t)b * M_SZ;
    const float* p1 = p0 + (size_t)B_SZ * M_SZ;
    const float* p2 = p1 + (size_t)B_SZ * M_SZ;

    float x0 = p0[tid]       + p1[tid]       + p2[tid]       + src[(size_t)b * D_SZ + tid];
    float x1 = p0[tid + 256] + p1[tid + 256] + p2[tid + 256];
    float x2 = p0[tid + 512] + p1[tid + 512] + p2[tid + 512] + src_t[(size_t)b * D_SZ + tid];

    float s = x0 + x1 + x2;
    #pragma unroll
    for (int o = 16; o > 0; o >>= 1) s += __shfl_xor_sync(0xffffffffu, s, o);
    if (lane == 0) red[wrp] = s;
    __syncthreads();
    float mu = (red[0]+red[1]+red[2]+red[3]+red[4]+red[5]+red[6]+red[7]) * (1.0f/768.0f);
    __syncthreads();

    float d0 = x0 - mu, d1 = x1 - mu, d2 = x2 - mu;
    float q = d0*d0 + d1*d1 + d2*d2;
    #pragma unroll
    for (int o = 16; o > 0; o >>= 1) q += __shfl_xor_sync(0xffffffffu, q, o);
    if (lane == 0) red[wrp] = q;
    __syncthreads();
    float var = (red[0]+red[1]+red[2]+red[3]+red[4]+red[5]+red[6]+red[7]) * (1.0f/768.0f);
    float rstd = rsqrtf(var + 1e-5f);

    float* xo = g_x + (size_t)b * (M_SZ + D_SZ);
    xo[tid]       = d0 * rstd * ln_w[tid]       + ln_b[tid];
    xo[tid + 256] = d1 * rstd * ln_w[tid + 256] + ln_b[tid + 256];
    xo[tid + 512] = d2 * rstd * ln_w[tid + 512] + ln_b[tid + 512];
    xo[768 + tid] = src[(size_t)b * D_SZ + tid];
}

__global__ __launch_bounds__(256) void reduce_relu_kernel()
{
    const int b = blockIdx.x;
    const int tid = threadIdx.x;
    const float* p0 = g_part + (size_t)b * M_SZ;
    const float* p1 = p0 + (size_t)B_SZ * M_SZ;
    const float* p2 = p1 + (size_t)B_SZ * M_SZ;
    float* y = g_y + (size_t)b * M_SZ;
    #pragma unroll
    for (int c = 0; c < 3; c++) {
        int f = tid + c * 256;
        y[f] = fmaxf(p0[f] + p1[f] + p2[f], 0.f);
    }
}

__global__ __launch_bounds__(256) void reduce_out_kernel(float* __restrict__ out)
{
    const int b = blockIdx.x;
    const int tid = threadIdx.x;
    float s = 0.f;
    #pragma unroll
    for (int z = 0; z < 8; z++)
        s += g_part[(size_t)z * B_SZ * D_SZ + (size_t)b * D_SZ + tid];
    out[(size_t)b * D_SZ + tid] = s;
}

// ---------------------------------------------------------------------------
extern "C" void kernel_launch(void* const* d_in, const int* in_sizes, int n_in,
                              void* d_out, int out_size)
{
    const float* src         = (const float*)d_in[0];
    const float* src_t       = (const float*)d_in[1];
    const float* seq         = (const float*)d_in[2];
    const float* seq_t       = (const float*)d_in[3];
    const float* seq_e       = (const float*)d_in[4];
    const unsigned int* mask = (const unsigned int*)d_in[5];
    const float* shared_attn = (const float*)d_in[6];
    const float* fc_w        = (const float*)d_in[7];
    const float* ln_w        = (const float*)d_in[8];
    const float* ln_b        = (const float*)d_in[9];
    const float* w1          = (const float*)d_in[10];
    const float* w2          = (const float*)d_in[11];

    float* out    = (float*)d_out;
    float* attn_w = out + (size_t)B_SZ * D_SZ;

    float* g_att_p;  cudaGetSymbolAddress((void**)&g_att_p, g_att);
    float* g_x_p;    cudaGetSymbolAddress((void**)&g_x_p, g_x);
    float* g_y_p;    cudaGetSymbolAddress((void**)&g_y_p, g_y);
    float* g_part_p; cudaGetSymbolAddress((void**)&g_part_p, g_part);

    cudaFuncSetAttribute(attn_kernel, cudaFuncAttributeMaxDynamicSharedMemorySize, ATTN_SMEM);

    attn_kernel<<<B_SZ, 256, ATTN_SMEM>>>(seq, seq_e, seq_t, mask, shared_attn, attn_w);

    gemm_tc_kernel<768, 3><<<dim3(8, 12, 3), 256>>>(g_att_p, fc_w, g_part_p, M_SZ);
    reduce_fc_ln_kernel<<<B_SZ, 256>>>(src, src_t, ln_w, ln_b);

    gemm_tc_kernel<1024, 3><<<dim3(8, 12, 3), 256>>>(g_x_p, w1, g_part_p, M_SZ);
    reduce_relu_kernel<<<B_SZ, 256>>>();

    gemm_tc_kernel<768, 8><<<dim3(8, 4, 8), 256>>>(g_y_p, w2, g_part_p, D_SZ);
    reduce_out_kernel<<<B_SZ, 256>>>(out);
}

// round 11
// speedup vs baseline: 1.4237x; 1.1471x over previous
#include <cuda_runtime.h>
#include <cstdint>

#define B_SZ 1024
#define N_SZ 256
#define D_SZ 256
#define M_SZ 768
#define NEG_VAL -1.0e10f

// Scratch (__device__ globals; no allocation allowed)
__device__ float g_att[B_SZ * M_SZ];              // attention output (B, 768)
__device__ float g_x[B_SZ * (M_SZ + D_SZ)];       // [LN(h), src]  (B, 1024)
__device__ float g_y[B_SZ * M_SZ];                // relu(x @ W1^T)
__device__ float g_part[3 * B_SZ * M_SZ];         // split-K partials

// ---------------------------------------------------------------------------
// K1: fused single-pass attention. Each K element is read from SMEM exactly
// once: threads pull their 3 owned features per row into registers, use them
// for BOTH the score partial (reduced via 9-shfl multi-row butterfly + 64-float
// SMEM stage) and the register-resident accumulate. cp.async double-buffered.
// ---------------------------------------------------------------------------
#define TROWS 8
// sK double buffer + s_all + ts + sp + sPP(64)
#define ATTN_SMEM ((2 * TROWS * M_SZ + N_SZ + TROWS + 12 + 64) * 4)

__device__ __forceinline__ void cp_async16(uint32_t saddr, const void* gaddr) {
    asm volatile("cp.async.cg.shared.global [%0], [%1], 16;\n" :: "r"(saddr), "l"(gaddr));
}
__device__ __forceinline__ void cp_commit() { asm volatile("cp.async.commit_group;\n"); }

__global__ __launch_bounds__(256) void attn_kernel(
    const float* __restrict__ seq, const float* __restrict__ seq_e,
    const float* __restrict__ seq_t, const unsigned int* __restrict__ mask,
    const float* __restrict__ shared_attn, float* __restrict__ attn_w_out)
{
    extern __shared__ float smem[];
    float* sK    = smem;                        // [2][TROWS][768]
    float* s_all = smem + 2 * TROWS * M_SZ;     // [256]
    float* ts    = s_all + N_SZ;                // [TROWS]
    float* sp    = ts + TROWS;                  // [TROWS + 1]
    float* sPP   = sp + TROWS + 4;              // [8 warps][8 rows]

    const int b    = blockIdx.x;
    const int tid  = threadIdx.x;
    const int lane = tid & 31;
    const int wrp  = tid >> 5;
    const size_t bbase = (size_t)b * N_SZ * D_SZ;

    // this thread's 3 wk weights (features 2*tid, 2*tid+1, 512+tid)
    const float wk0 = __ldg(shared_attn + M_SZ + 2 * tid);
    const float wk1 = __ldg(shared_attn + M_SZ + 2 * tid + 1);
    const float wk2 = __ldg(shared_attn + M_SZ + 512 + tid);

    float2 a01 = make_float2(0.f, 0.f);
    float  a2  = 0.f;
    float lsum = 0.f, mval = -3.0e38f;

    // issue tile 0 (8 rows x 768 floats = 1536 float4 / 256 threads = 6 chunks)
    {
        #pragma unroll
        for (int u = 0; u < 6; u++) {
            int idx = u * 256 + tid;
            int r   = idx / 192;
            int pos = idx - r * 192;
            int seg = pos >> 6;
            int j4  = pos & 63;
            const float* base = (seg == 0) ? seq : ((seg == 1) ? seq_e : seq_t);
            uint32_t sa = (uint32_t)__cvta_generic_to_shared(sK + (r * 192 + pos) * 4);
            cp_async16(sa, base + bbase + (size_t)r * D_SZ + j4 * 4);
        }
        cp_commit();
    }

    for (int t = 0; t < N_SZ / TROWS; t++) {
        const int cur = t & 1;
        if (t + 1 < N_SZ / TROWS) {
            const int nxt = (t + 1) & 1;
            const int n0n = (t + 1) * TROWS;
            #pragma unroll
            for (int u = 0; u < 6; u++) {
                int idx = u * 256 + tid;
                int r   = idx / 192;
                int pos = idx - r * 192;
                int seg = pos >> 6;
                int j4  = pos & 63;
                const float* base = (seg == 0) ? seq : ((seg == 1) ? seq_e : seq_t);
                uint32_t sa = (uint32_t)__cvta_generic_to_shared(
                    sK + (nxt * TROWS * M_SZ) + (r * 192 + pos) * 4);
                cp_async16(sa, base + bbase + (size_t)(n0n + r) * D_SZ + j4 * 4);
            }
            cp_commit();
            asm volatile("cp.async.wait_group 1;\n");
        } else {
            asm volatile("cp.async.wait_group 0;\n");
        }
        __syncthreads();                        // sync1: tile visible

        const float* kb = sK + cur * TROWS * M_SZ;
        const int n0 = t * TROWS;

        // ---- single SMEM read: own features per row -> registers ----
        float2 kv2[TROWS];
        float  kv1[TROWS];
        float  v[TROWS];
        #pragma unroll
        for (int r = 0; r < TROWS; r++) {
            const float* kr = kb + r * M_SZ;
            kv2[r] = *(const float2*)(kr + 2 * tid);
            kv1[r] = kr[512 + tid];
            v[r] = kv2[r].x * wk0 + kv2[r].y * wk1 + kv1[r] * wk2;
        }

        // ---- multi-row warp butterfly: 9 shfl reduce 8 rows over 32 lanes ----
        {
            float w4[4];
            const bool h16 = (lane & 16) != 0;
            #pragma unroll
            for (int j = 0; j < 4; j++) {
                float snd = h16 ? v[j] : v[j + 4];
                float rc  = __shfl_xor_sync(0xffffffffu, snd, 16);
                w4[j] = (h16 ? v[j + 4] : v[j]) + rc;
            }
            float w2[2];
            const bool h8 = (lane & 8) != 0;
            #pragma unroll
            for (int j = 0; j < 2; j++) {
                float snd = h8 ? w4[j] : w4[j + 2];
                float rc  = __shfl_xor_sync(0xffffffffu, snd, 8);
                w2[j] = (h8 ? w4[j + 2] : w4[j]) + rc;
            }
            const bool h4 = (lane & 4) != 0;
            float snd = h4 ? w2[0] : w2[1];
            float rc  = __shfl_xor_sync(0xffffffffu, snd, 4);
            float y   = (h4 ? w2[1] : w2[0]) + rc;
            y += __shfl_xor_sync(0xffffffffu, y, 2);
            y += __shfl_xor_sync(0xffffffffu, y, 1);
            // lane>>2 holds row (lane>>2); one lane per group writes
            if ((lane & 3) == 0) sPP[wrp * 8 + (lane >> 2)] = y;
        }
        __syncthreads();                        // sync2: partials visible

        // ---- warp 0 folds 8 warps, applies mask, publishes scores ----
        if (wrp == 0 && lane < TROWS) {
            float tot = 0.f;
            #pragma unroll
            for (int w = 0; w < 8; w++) tot += sPP[w * 8 + lane];
            int n = n0 + lane;
            float s = (mask[(size_t)b * N_SZ + n] != 0u) ? NEG_VAL : tot;
            ts[lane]  = s;
            s_all[n]  = s;
        }
        __syncthreads();                        // sync3: ts visible

        float mt = mval;
        #pragma unroll
        for (int r = 0; r < TROWS; r++) mt = fmaxf(mt, ts[r]);

        if (wrp == 0) {
            float pv = (lane < TROWS) ? __expf(ts[lane] - mt) : 0.f;
            float tot = pv;
            #pragma unroll
            for (int o = 16; o > 0; o >>= 1) tot += __shfl_xor_sync(0xffffffffu, tot, o);
            if (lane < TROWS) sp[lane] = pv;
            if (lane == 0)    sp[TROWS] = tot;
        }
        if (mt > mval) {
            float sc = __expf(mval - mt);
            a01.x *= sc; a01.y *= sc; a2 *= sc; lsum *= sc;
            mval = mt;
        }
        __syncthreads();                        // sync4: sp visible

        lsum += sp[TROWS];
        #pragma unroll
        for (int r = 0; r < TROWS; r++) {
            float p = sp[r];
            a01.x = fmaf(p, kv2[r].x, a01.x);
            a01.y = fmaf(p, kv2[r].y, a01.y);
            a2    = fmaf(p, kv1[r],   a2);
        }
        // no trailing sync needed: all reads of this buffer happened before
        // sync2; next overwrite of it is issued after the next loop's entry.
    }

    float inv = 1.0f / lsum;
    attn_w_out[(size_t)b * N_SZ + tid] = __expf(s_all[tid] - mval) * inv;
    float* o = g_att + (size_t)b * M_SZ;
    *(float2*)(o + 2 * tid) = make_float2(a01.x * inv, a01.y * inv);
    o[512 + tid] = a2 * inv;
}

// ---------------------------------------------------------------------------
// Split-K tf32 tensor-core GEMM (unchanged from R10 passing version).
// ---------------------------------------------------------------------------
__device__ __forceinline__ uint32_t f2tf32(float x) {
    uint32_t r; asm("cvt.rna.tf32.f32 %0, %1;\n" : "=r"(r) : "f"(x)); return r;
}
__device__ __forceinline__ void mma_tf32(float* c, const uint32_t* a, const uint32_t* b) {
    asm volatile(
        "mma.sync.aligned.m16n8k8.row.col.f32.tf32.tf32.f32 "
        "{%0,%1,%2,%3}, {%4,%5,%6,%7}, {%8,%9}, {%0,%1,%2,%3};\n"
        : "+f"(c[0]), "+f"(c[1]), "+f"(c[2]), "+f"(c[3])
        : "r"(a[0]), "r"(a[1]), "r"(a[2]), "r"(a[3]), "r"(b[0]), "r"(b[1]));
}

template <int KD, int S>
__global__ __launch_bounds__(256, 2) void gemm_tc_kernel(
    const float* __restrict__ A, const float* __restrict__ W,
    float* __restrict__ part, int Nout)
{
    __shared__ __align__(16) uint32_t sA[128 * 36];
    __shared__ __align__(16) uint32_t sW[64 * 36];

    const int tid  = threadIdx.x;
    const int wid  = tid >> 5, lane = tid & 31;
    const int g    = lane >> 2, tg = lane & 3;
    const int wm   = wid & 1,  wn  = wid >> 1;
    const int m0   = blockIdx.x * 128;
    const int n0   = blockIdx.y * 64;
    const int z    = blockIdx.z;
    constexpr int KT = KD / 32;
    const int kt0 = z * KT / S;
    const int kt1 = (z + 1) * KT / S;

    const int ra_r = tid >> 3, ra_j = tid & 7;
    float4 ra[4], rw[2];

    {
        const int kc = kt0 * 32;
        #pragma unroll
        for (int u = 0; u < 4; u++)
            ra[u] = __ldg((const float4*)(A + (size_t)(m0 + u * 32 + ra_r) * KD + kc) + ra_j);
        #pragma unroll
        for (int u = 0; u < 2; u++)
            rw[u] = __ldg((const float4*)(W + (size_t)(n0 + u * 32 + ra_r) * KD + kc) + ra_j);
    }

    float acc[4][2][4];
    #pragma unroll
    for (int mi = 0; mi < 4; mi++)
        #pragma unroll
        for (int ni = 0; ni < 2; ni++)
            #pragma unroll
            for (int f = 0; f < 4; f++) acc[mi][ni][f] = 0.f;

    for (int kt = kt0; kt < kt1; kt++) {
        #pragma unroll
        for (int u = 0; u < 4; u++) {
            uint4 v = make_uint4(f2tf32(ra[u].x), f2tf32(ra[u].y), f2tf32(ra[u].z), f2tf32(ra[u].w));
            *(uint4*)(sA + (u * 32 + ra_r) * 36 + ra_j * 4) = v;
        }
        #pragma unroll
        for (int u = 0; u < 2; u++) {
            uint4 v = make_uint4(f2tf32(rw[u].x), f2tf32(rw[u].y), f2tf32(rw[u].z), f2tf32(rw[u].w));
            *(uint4*)(sW + (u * 32 + ra_r) * 36 + ra_j * 4) = v;
        }
        __syncthreads();

        if (kt + 1 < kt1) {
            const int kc = (kt + 1) * 32;
            #pragma unroll
            for (int u = 0; u < 4; u++)
                ra[u] = __ldg((const float4*)(A + (size_t)(m0 + u * 32 + ra_r) * KD + kc) + ra_j);
            #pragma unroll
            for (int u = 0; u < 2; u++)
                rw[u] = __ldg((const float4*)(W + (size_t)(n0 + u * 32 + ra_r) * KD + kc) + ra_j);
        }

        #pragma unroll
        for (int ks = 0; ks < 4; ks++) {
            const int kb = ks * 8;
            uint32_t bfrag[2][2];
            #pragma unroll
            for (int ni = 0; ni < 2; ni++) {
                const int n = wn * 16 + ni * 8;
                bfrag[ni][0] = sW[(n + g) * 36 + kb + tg];
                bfrag[ni][1] = sW[(n + g) * 36 + kb + tg + 4];
            }
            #pragma unroll
            for (int mi = 0; mi < 4; mi++) {
                const int m = wm * 64 + mi * 16;
                uint32_t afrag[4];
                afrag[0] = sA[(m + g)     * 36 + kb + tg];
                afrag[1] = sA[(m + g + 8) * 36 + kb + tg];
                afrag[2] = sA[(m + g)     * 36 + kb + tg + 4];
                afrag[3] = sA[(m + g + 8) * 36 + kb + tg + 4];
                #pragma unroll
                for (int ni = 0; ni < 2; ni++)
                    mma_tf32(acc[mi][ni], afrag, bfrag[ni]);
            }
        }
        __syncthreads();
    }

    float* p = part + (size_t)z * B_SZ * Nout;
    #pragma unroll
    for (int mi = 0; mi < 4; mi++) {
        const int m = m0 + wm * 64 + mi * 16;
        #pragma unroll
        for (int ni = 0; ni < 2; ni++) {
            const int n = n0 + wn * 16 + ni * 8 + tg * 2;
            *(float2*)(p + (size_t)(m + g)     * Nout + n) = make_float2(acc[mi][ni][0], acc[mi][ni][1]);
            *(float2*)(p + (size_t)(m + g + 8) * Nout + n) = make_float2(acc[mi][ni][2], acc[mi][ni][3]);
        }
    }
}

// ---------------------------------------------------------------------------
// Reduce kernels (fold split-K partials + epilogue)
// ---------------------------------------------------------------------------
__global__ __launch_bounds__(256) void reduce_fc_ln_kernel(
    const float* __restrict__ src, const float* __restrict__ src_t,
    const float* __restrict__ ln_w, const float* __restrict__ ln_b)
{
    __shared__ float red[8];
    const int b = blockIdx.x;
    const int tid = threadIdx.x;
    const int lane = tid & 31, wrp = tid >> 5;

    const float* p0 = g_part + (size_t)b * M_SZ;
    const float* p1 = p0 + (size_t)B_SZ * M_SZ;
    const float* p2 = p1 + (size_t)B_SZ * M_SZ;

    float x0 = p0[tid]       + p1[tid]       + p2[tid]       + src[(size_t)b * D_SZ + tid];
    float x1 = p0[tid + 256] + p1[tid + 256] + p2[tid + 256];
    float x2 = p0[tid + 512] + p1[tid + 512] + p2[tid + 512] + src_t[(size_t)b * D_SZ + tid];

    float s = x0 + x1 + x2;
    #pragma unroll
    for (int o = 16; o > 0; o >>= 1) s += __shfl_xor_sync(0xffffffffu, s, o);
    if (lane == 0) red[wrp] = s;
    __syncthreads();
    float mu = (red[0]+red[1]+red[2]+red[3]+red[4]+red[5]+red[6]+red[7]) * (1.0f/768.0f);
    __syncthreads();

    float d0 = x0 - mu, d1 = x1 - mu, d2 = x2 - mu;
    float q = d0*d0 + d1*d1 + d2*d2;
    #pragma unroll
    for (int o = 16; o > 0; o >>= 1) q += __shfl_xor_sync(0xffffffffu, q, o);
    if (lane == 0) red[wrp] = q;
    __syncthreads();
    float var = (red[0]+red[1]+red[2]+red[3]+red[4]+red[5]+red[6]+red[7]) * (1.0f/768.0f);
    float rstd = rsqrtf(var + 1e-5f);

    float* xo = g_x + (size_t)b * (M_SZ + D_SZ);
    xo[tid]       = d0 * rstd * ln_w[tid]       + ln_b[tid];
    xo[tid + 256] = d1 * rstd * ln_w[tid + 256] + ln_b[tid + 256];
    xo[tid + 512] = d2 * rstd * ln_w[tid + 512] + ln_b[tid + 512];
    xo[768 + tid] = src[(size_t)b * D_SZ + tid];
}

__global__ __launch_bounds__(256) void reduce_relu_kernel()
{
    const int b = blockIdx.x;
    const int tid = threadIdx.x;
    const float* p0 = g_part + (size_t)b * M_SZ;
    const float* p1 = p0 + (size_t)B_SZ * M_SZ;
    const float* p2 = p1 + (size_t)B_SZ * M_SZ;
    float* y = g_y + (size_t)b * M_SZ;
    #pragma unroll
    for (int c = 0; c < 3; c++) {
        int f = tid + c * 256;
        y[f] = fmaxf(p0[f] + p1[f] + p2[f], 0.f);
    }
}

__global__ __launch_bounds__(256) void reduce_out_kernel(float* __restrict__ out)
{
    const int b = blockIdx.x;
    const int tid = threadIdx.x;
    float s = 0.f;
    #pragma unroll
    for (int z = 0; z < 8; z++)
        s += g_part[(size_t)z * B_SZ * D_SZ + (size_t)b * D_SZ + tid];
    out[(size_t)b * D_SZ + tid] = s;
}

// ---------------------------------------------------------------------------
extern "C" void kernel_launch(void* const* d_in, const int* in_sizes, int n_in,
                              void* d_out, int out_size)
{
    const float* src         = (const float*)d_in[0];
    const float* src_t       = (const float*)d_in[1];
    const float* seq         = (const float*)d_in[2];
    const float* seq_t       = (const float*)d_in[3];
    const float* seq_e       = (const float*)d_in[4];
    const unsigned int* mask = (const unsigned int*)d_in[5];
    const float* shared_attn = (const float*)d_in[6];
    const float* fc_w        = (const float*)d_in[7];
    const float* ln_w        = (const float*)d_in[8];
    const float* ln_b        = (const float*)d_in[9];
    const float* w1          = (const float*)d_in[10];
    const float* w2          = (const float*)d_in[11];

    float* out    = (float*)d_out;
    float* attn_w = out + (size_t)B_SZ * D_SZ;

    float* g_att_p;  cudaGetSymbolAddress((void**)&g_att_p, g_att);
    float* g_x_p;    cudaGetSymbolAddress((void**)&g_x_p, g_x);
    float* g_y_p;    cudaGetSymbolAddress((void**)&g_y_p, g_y);
    float* g_part_p; cudaGetSymbolAddress((void**)&g_part_p, g_part);

    cudaFuncSetAttribute(attn_kernel, cudaFuncAttributeMaxDynamicSharedMemorySize, ATTN_SMEM);

    attn_kernel<<<B_SZ, 256, ATTN_SMEM>>>(seq, seq_e, seq_t, mask, shared_attn, attn_w);

    gemm_tc_kernel<768, 3><<<dim3(8, 12, 3), 256>>>(g_att_p, fc_w, g_part_p, M_SZ);
    reduce_fc_ln_kernel<<<B_SZ, 256>>>(src, src_t, ln_w, ln_b);

    gemm_tc_kernel<1024, 3><<<dim3(8, 12, 3), 256>>>(g_x_p, w1, g_part_p, M_SZ);
    reduce_relu_kernel<<<B_SZ, 256>>>();

    gemm_tc_kernel<768, 8><<<dim3(8, 4, 8), 256>>>(g_y_p, w2, g_part_p, D_SZ);
    reduce_out_kernel<<<B_SZ, 256>>>(out);
}